// round 14
// baseline (speedup 1.0000x reference)
#include <cuda_runtime.h>
#include <cstdint>

// ---------------------------------------------------------------------------
// Problem constants
// ---------------------------------------------------------------------------
#define B 64
#define N 2048
#define DIM 768
#define POOL 1024
#define LEN 16
#define NOUT 2080                 // 2*LEN + N
#define C4 (DIM / 4)              // 192 float4 per row
#define NCHUNK 32
#define TOKPC (N / NCHUNK)        // 64
#define SCALAR_OFF ((size_t)B * NOUT * DIM)
#define KSTRIPE (DIM / 8)         // 96 k's per warp in sim

// ---------------------------------------------------------------------------
// Device scratch (no allocations). Only touched from device code — passing
// these symbols from host binds the host shadow copy (ATS trap).
// ---------------------------------------------------------------------------
__device__ __align__(16) float4 g_part[B * NCHUNK * C4];  // per-(b,chunk) sums
__device__ __align__(16) float  g_xnormT[DIM * B];        // x_norm^T [c][b]
__device__ __align__(16) float  g_residT[DIM * B];        // residual^T [c][b]
__device__ __align__(16) float  g_sim[B * POOL];          // sim [b][p]
__device__ __align__(16) float  g_rsim[B * POOL];         // res-sim [b][p]
__device__ unsigned long long   g_pack1[B];  // (flip(best)<<32)|~idx, stage 0
__device__ unsigned long long   g_pack2[B];  // stage 1

// ---------------------------------------------------------------------------
// order-monotonic float<->u32 mapping + pack/unpack. max(pack) == max value;
// ties -> lowest pool index (low word = ~idx). flip(v) > 0 for all finite v,
// so the re-armed 0 cells are always overwritten before any unpack.
// ---------------------------------------------------------------------------
__device__ __forceinline__ unsigned flip_f(float v) {
    unsigned b = __float_as_uint(v);
    return b ^ ((b & 0x80000000u) ? 0xffffffffu : 0x80000000u);
}
__device__ __forceinline__ float unflip_f(unsigned k) {
    return __uint_as_float(k ^ ((k & 0x80000000u) ? 0x80000000u : 0xffffffffu));
}
__device__ __forceinline__ unsigned long long pack_vi(float v, int idx) {
    return ((unsigned long long)flip_f(v) << 32) |
           (unsigned long long)(0xffffffffu - (unsigned)idx);
}
__device__ __forceinline__ int unpack_idx(unsigned long long p) {
    return (int)(0xffffffffu - (unsigned)(p & 0xffffffffu));
}
__device__ __forceinline__ float unpack_val(unsigned long long p) {
    return unflip_f((unsigned)(p >> 32));
}

// ---------------------------------------------------------------------------
// 1) Fused: copy x_embed -> out rows [32,2080) AND per-(b,chunk,c) sums.
//    grid = B*32 = 2048, block = 192. (Byte-identical to R9/R12 best.)
// ---------------------------------------------------------------------------
__global__ __launch_bounds__(C4) void copy_mean_kernel(
    const float4* __restrict__ x, float4* __restrict__ out4)
{
    int b     = blockIdx.x >> 5;
    int chunk = blockIdx.x & 31;
    int c4    = threadIdx.x;                         // 0..191

    size_t xbase = ((size_t)b * N + (size_t)chunk * TOKPC) * C4 + c4;
    size_t obase = ((size_t)b * NOUT + 2 * LEN + (size_t)chunk * TOKPC) * C4 + c4;

    float ax = 0.f, ay = 0.f, az = 0.f, aw = 0.f;
#pragma unroll 8
    for (int t = 0; t < TOKPC; ++t) {
        float4 v = x[xbase + (size_t)t * C4];
        out4[obase + (size_t)t * C4] = v;
        ax += v.x; ay += v.y; az += v.z; aw += v.w;
    }
    g_part[(b * NCHUNK + chunk) * C4 + c4] = make_float4(ax, ay, az, aw);
}

// ---------------------------------------------------------------------------
// 2) x_norm = l2norm(mean) -> g_xnormT (transposed); re-arms the per-batch
//    atomic-max cells for this replay.  grid=B, block=256. PDL.
// ---------------------------------------------------------------------------
__global__ __launch_bounds__(256) void xnorm_kernel()
{
    cudaGridDependencySynchronize();
    __shared__ float sh[8];
    int tid = threadIdx.x;
    int warp = tid >> 5, lane = tid & 31;
    int b = blockIdx.x;
    if (tid == 0) { g_pack1[b] = 0ull; g_pack2[b] = 0ull; }
    int c4 = tid;
    float sx = 0.f, sy = 0.f, sz = 0.f, sw = 0.f;
    if (c4 < C4) {
#pragma unroll
        for (int k = 0; k < NCHUNK; ++k) {
            float4 p = g_part[(b * NCHUNK + k) * C4 + c4];
            sx += p.x; sy += p.y; sz += p.z; sw += p.w;
        }
        const float invN = 1.0f / (float)N;
        sx *= invN; sy *= invN; sz *= invN; sw *= invN;
    }
    float ss = sx * sx + sy * sy + sz * sz + sw * sw;
#pragma unroll
    for (int o = 16; o > 0; o >>= 1) ss += __shfl_down_sync(0xffffffffu, ss, o);
    if (lane == 0) sh[warp] = ss;
    __syncthreads();
    if (tid == 0) {
        float tot = 0.f;
#pragma unroll
        for (int w = 0; w < 8; ++w) tot += sh[w];
        sh[0] = rsqrtf(fmaxf(tot, 1e-12f));
    }
    __syncthreads();
    if (c4 < C4) {
        float inv = sh[0];
        int c = c4 * 4;
        g_xnormT[(c + 0) * B + b] = sx * inv;
        g_xnormT[(c + 1) * B + b] = sy * inv;
        g_xnormT[(c + 2) * B + b] = sz * inv;
        g_xnormT[(c + 3) * B + b] = sw * inv;
    }
}

// ---------------------------------------------------------------------------
// 3) sim[b][p] = dot(vec[b], key[p]) * rsqrt(max(||key[p]||^2, eps))
//    PDL: key rows staged to smem BEFORE the dependency sync (overlaps the
//    predecessor's tail). Block = 2 pool rows; 8 warps split k; lane owns a
//    batch pair.  grid = POOL/2 = 512, block = 256.
// ---------------------------------------------------------------------------
template <int STAGE>
__global__ __launch_bounds__(256) void sim_kernel(const float* __restrict__ keys)
{
    __shared__ float  skey[2][DIM];                    // 6 KB
    __shared__ float4 spart[8][32];
    __shared__ float2 snorm[8];

    int p0   = blockIdx.x * 2;
    int tid  = threadIdx.x;
    int warp = tid >> 5, lane = tid & 31;

    // ---- independent prefetch: key rows (keys are kernel inputs) ----
    {
        const float4* kr = (const float4*)(keys + (size_t)p0 * DIM);
#pragma unroll
        for (int i = tid; i < 2 * C4; i += 256) {
            ((float4*)skey)[i] = __ldg(kr + i);
        }
    }
    cudaGridDependencySynchronize();                   // vecT now valid
    __syncthreads();

    const float* vecT = STAGE ? g_residT : g_xnormT;   // [DIM][B]
    float*       simB = STAGE ? g_rsim   : g_sim;      // [B][POOL]
    const float2* xv  = (const float2*)vecT + lane;    // +k*(B/2)

    float a0x = 0.f, a0y = 0.f, a1x = 0.f, a1y = 0.f;
    float ss0 = 0.f, ss1 = 0.f;                        // identical across lanes
    int kb = warp * KSTRIPE;
#pragma unroll 8
    for (int i = 0; i < KSTRIPE; ++i) {
        int k = kb + i;
        float  kv0 = skey[0][k];
        float  kv1 = skey[1][k];
        ss0 += kv0 * kv0;
        ss1 += kv1 * kv1;
        float2 x = xv[(size_t)k * (B / 2)];
        a0x += kv0 * x.x; a0y += kv0 * x.y;
        a1x += kv1 * x.x; a1y += kv1 * x.y;
    }
    spart[warp][lane] = make_float4(a0x, a0y, a1x, a1y);
    if (lane == 0) snorm[warp] = make_float2(ss0, ss1);
    __syncthreads();
    if (warp == 0) {
        float sx = 0.f, sy = 0.f, tx = 0.f, ty = 0.f;
        float n0 = 0.f, n1 = 0.f;
#pragma unroll
        for (int w = 0; w < 8; ++w) {
            float4 v = spart[w][lane];
            sx += v.x; sy += v.y; tx += v.z; ty += v.w;
            n0 += snorm[w].x; n1 += snorm[w].y;
        }
        float i0 = rsqrtf(fmaxf(n0, 1e-12f));
        float i1 = rsqrtf(fmaxf(n1, 1e-12f));
        int b0 = lane * 2;
        simB[(size_t)b0 * POOL + p0]           = sx * i0;
        simB[(size_t)(b0 + 1) * POOL + p0]     = sy * i0;
        simB[(size_t)b0 * POOL + p0 + 1]       = tx * i1;
        simB[(size_t)(b0 + 1) * POOL + p0 + 1] = ty * i1;
    }
}

// ---------------------------------------------------------------------------
// 4) argmax, wide: 4 blocks per batch, each reduces a 256-entry quarter-row
//    (1 KB coalesced) and fires ONE packed RED.MAX per block. Ties -> lowest
//    p via ~idx in the low word; fully order-independent -> deterministic.
//    grid = 4*B = 256, block = 256. PDL.
// ---------------------------------------------------------------------------
template <int STAGE>
__global__ __launch_bounds__(256) void argmax_kernel()
{
    cudaGridDependencySynchronize();
    __shared__ float swv[8];
    __shared__ int   swi[8];
    int b = blockIdx.x >> 2;
    int q = blockIdx.x & 3;
    int tid = threadIdx.x;
    int warp = tid >> 5, lane = tid & 31;

    const float* simRow = (STAGE ? g_rsim : g_sim) + (size_t)b * POOL + q * 256;
    float best = simRow[tid];
    int   bi   = q * 256 + tid;

#pragma unroll
    for (int o = 16; o > 0; o >>= 1) {
        float vo = __shfl_down_sync(0xffffffffu, best, o);
        int   io = __shfl_down_sync(0xffffffffu, bi, o);
        if (vo > best || (vo == best && io < bi)) { best = vo; bi = io; }
    }
    if (lane == 0) { swv[warp] = best; swi[warp] = bi; }
    __syncthreads();
    if (tid == 0) {
        float v = swv[0]; int id = swi[0];
#pragma unroll
        for (int w = 1; w < 8; ++w) {
            if (swv[w] > v || (swv[w] == v && swi[w] < id)) {
                v = swv[w]; id = swi[w];
            }
        }
        atomicMax(STAGE ? &g_pack2[b] : &g_pack1[b], pack_vi(v, id));
    }
}

// ---------------------------------------------------------------------------
// 5) residT via 32x32 smem transpose: coalesced reads of pk rows AND
//    coalesced writes of residT. grid = 24*2 = 48, block = (32,32). PDL.
//    residT[c][b] = pk[idx1[b]][c] - xnormT[c][b]
// ---------------------------------------------------------------------------
__global__ void resid_kernel(const float* __restrict__ pk)
{
    cudaGridDependencySynchronize();
    __shared__ float tile[32][33];
    __shared__ int   sidx[32];
    int ct = blockIdx.x % (DIM / 32);     // 0..23
    int bt = blockIdx.x / (DIM / 32);     // 0..1
    int c0 = ct * 32, b0 = bt * 32;
    int tx = threadIdx.x, ty = threadIdx.y;

    if (ty == 0) sidx[tx] = unpack_idx(g_pack1[b0 + tx]);
    __syncthreads();
    // read: row b = b0+ty, cols c0+tx (128B coalesced per warp)
    tile[ty][tx] = pk[(size_t)sidx[ty] * DIM + c0 + tx];
    __syncthreads();
    // write: c = c0+ty, b = b0+tx (128B coalesced per warp)
    g_residT[(c0 + ty) * B + b0 + tx] =
        tile[tx][ty] - g_xnormT[(c0 + ty) * B + b0 + tx];
}

// ---------------------------------------------------------------------------
// 6) finish: both gathers spread over 256 blocks + scalar in block 256. PDL.
//    which=0 -> residual_prompt[idx2] @ out rows [0,16)
//    which=1 -> prompt[idx1]          @ out rows [16,32)
// ---------------------------------------------------------------------------
__global__ __launch_bounds__(256) void finish_kernel(
    const float4* __restrict__ prompt4,
    const float4* __restrict__ rprompt4,
    float4* __restrict__ out4,
    float* __restrict__ out_scalar,
    int write_scalar)
{
    cudaGridDependencySynchronize();
    if (blockIdx.x == 4 * B) {
        __shared__ float sh[2];
        if (write_scalar && threadIdx.x < 64) {
            float v = unpack_val(g_pack1[threadIdx.x]) +
                      unpack_val(g_pack2[threadIdx.x]);
#pragma unroll
            for (int o = 16; o > 0; o >>= 1)
                v += __shfl_down_sync(0xffffffffu, v, o);
            if ((threadIdx.x & 31) == 0) sh[threadIdx.x >> 5] = v;
        }
        __syncthreads();
        if (write_scalar && threadIdx.x == 0)
            out_scalar[SCALAR_OFF] = (sh[0] + sh[1]) * (1.0f / (float)B);
        return;
    }
    int b     = blockIdx.x >> 2;
    int which = (blockIdx.x >> 1) & 1;
    int half  = blockIdx.x & 1;
    int idx = which ? unpack_idx(g_pack1[b]) : unpack_idx(g_pack2[b]);
    const int HQ = (LEN / 2) * C4;                   // 1536 float4 per half
    const float4* src = (which ? prompt4 : rprompt4)
                        + (size_t)idx * LEN * C4 + (size_t)half * HQ;
    float4* dst = out4 + ((size_t)b * NOUT + (which ? LEN : 0)
                          + (size_t)half * (LEN / 2)) * C4;
#pragma unroll
    for (int i = 0; i < HQ / 256; ++i)
        dst[threadIdx.x + i * 256] = src[threadIdx.x + i * 256];
}

// ---------------------------------------------------------------------------
// PDL launch helper
// ---------------------------------------------------------------------------
template <typename K, typename... Args>
static void launch_pdl(dim3 grid, dim3 block, K kernel, Args... args)
{
    cudaLaunchConfig_t cfg = {};
    cfg.gridDim = grid;
    cfg.blockDim = block;
    cfg.dynamicSmemBytes = 0;
    cfg.stream = 0;                      // legacy default (capture) stream
    cudaLaunchAttribute attr[1];
    attr[0].id = cudaLaunchAttributeProgrammaticStreamSerialization;
    attr[0].val.programmaticStreamSerializationAllowed = 1;
    cfg.attrs = attr;
    cfg.numAttrs = 1;
    cudaLaunchKernelEx(&cfg, kernel, args...);
}

// ---------------------------------------------------------------------------
// launch
// ---------------------------------------------------------------------------
extern "C" void kernel_launch(void* const* d_in, const int* in_sizes, int n_in,
                              void* d_out, int out_size)
{
    // Map inputs by element count (order-robust).
    const float* x_embed = nullptr;
    const float* prompt = nullptr, * rprompt = nullptr;
    const float* pkey = nullptr, * rpkey = nullptr;
    for (int i = 0; i < n_in; ++i) {
        int sz = in_sizes[i];
        if (sz == B * N * DIM) x_embed = (const float*)d_in[i];
        else if (sz == POOL * LEN * DIM) {
            if (!prompt) prompt = (const float*)d_in[i];
            else if (!rprompt) rprompt = (const float*)d_in[i];
        } else if (sz == POOL * DIM) {
            if (!pkey) pkey = (const float*)d_in[i];
            else if (!rpkey) rpkey = (const float*)d_in[i];
        }
    }
    float* out = (float*)d_out;

    copy_mean_kernel<<<B * NCHUNK, C4>>>((const float4*)x_embed, (float4*)out);
    launch_pdl(dim3(B), dim3(256), xnorm_kernel);
    launch_pdl(dim3(POOL / 2), dim3(256), sim_kernel<0>, pkey);
    launch_pdl(dim3(4 * B), dim3(256), argmax_kernel<0>);
    launch_pdl(dim3(2 * DIM / 32), dim3(32, 32), resid_kernel, pkey);
    launch_pdl(dim3(POOL / 2), dim3(256), sim_kernel<1>, rpkey);
    launch_pdl(dim3(4 * B), dim3(256), argmax_kernel<1>);
    int write_scalar = ((size_t)out_size > SCALAR_OFF) ? 1 : 0;
    launch_pdl(dim3(4 * B + 1), dim3(256), finish_kernel,
               (const float4*)prompt, (const float4*)rprompt, (float4*)out,
               out, write_scalar);
}